// round 3
// baseline (speedup 1.0000x reference)
#include <cuda_runtime.h>
#include <cuda_bf16.h>

// Problem constants
#define NB     16
#define ENC_T  512
#define DEC_T  1024
#define NDIM   512
#define KW     31
#define PADW   15
#define PADLEN (ENC_T + 2*PADW + 2)   // 544 (rounded up)
#define NCTAS  128
#define NTHR   512
// smem layout (floats)
#define SM_W      0          // 512*64 = 32768
#define SM_WL     32768      // 512
#define SM_Q      33280      // 512
#define SM_SSC    33792      // 96
#define SM_SCU    33888      // 96
#define SM_RED    33984      // 512
#define SM_SCORE  34496      // 512
#define SM_WRED   35008      // 32
#define SM_FLOATS 35040
#define SM_BYTES  (SM_FLOATS * 4)

typedef unsigned long long u64;

// ---------- packed f32x2 helpers (B300 FFMA2 path) ----------
__device__ __forceinline__ u64 pack2(float x, float y) {
    u64 r;
    asm("mov.b64 %0, {%1, %2};" : "=l"(r)
        : "r"(__float_as_uint(x)), "r"(__float_as_uint(y)));
    return r;
}
__device__ __forceinline__ void unpack2(u64 v, float& x, float& y) {
    unsigned a, b;
    asm("mov.b64 {%0, %1}, %2;" : "=r"(a), "=r"(b) : "l"(v));
    x = __uint_as_float(a); y = __uint_as_float(b);
}
__device__ __forceinline__ u64 ffma2(u64 a, u64 b, u64 c) {
    u64 d;
    asm("fma.rn.f32x2 %0, %1, %2, %3;" : "=l"(d) : "l"(a), "l"(b), "l"(c));
    return d;
}
__device__ __forceinline__ u64 fadd2(u64 a, u64 b) {
    u64 d;
    asm("add.rn.f32x2 %0, %1, %2;" : "=l"(d) : "l"(a), "l"(b));
    return d;
}

// ---------- persistent state (no cudaMalloc allowed) ----------
__device__ float    g_score_pad[NB][PADLEN];
__device__ float    g_cum_pad[NB][PADLEN];
__device__ float    g_q[NB][NDIM];
__device__ float    g_logits[NB][ENC_T];
__device__ unsigned g_bar_count = 0;

// ---------- grid barrier: monotonic counter, acquire-polled ----------
__device__ __forceinline__ void grid_barrier(unsigned& target) {
    __syncthreads();
    if (threadIdx.x == 0) {
        __threadfence();                 // drain my CTA's stores to L2
        target += (unsigned)NCTAS;
        atomicAdd(&g_bar_count, 1u);
        unsigned cur;
        for (;;) {
            asm volatile("ld.acquire.gpu.u32 %0, [%1];"
                         : "=r"(cur) : "l"(&g_bar_count));
            if ((int)(cur - target) >= 0) break;
            __nanosleep(64);
        }
    }
    __syncthreads();
}

__device__ __forceinline__ float fast_tanh(float x) {
    // tanh(x) = 1 - 2/(exp(2x)+1); rel err ~1e-6, saturates correctly at +/-inf
    float e = __expf(x + x);
    return 1.0f - __fdividef(2.0f, e + 1.0f);
}

// ---------- init kernel: per-replay state reset ----------
__global__ void attn_init(const float* __restrict__ mel,
                          const int*   __restrict__ out_len) {
    int b = blockIdx.x, tid = threadIdx.x;
    if (b == 0 && tid == 0) g_bar_count = 0;
    for (int i = tid; i < PADLEN; i += NTHR) {
        g_score_pad[b][i] = 0.0f;
        g_cum_pad[b][i]   = 0.0f;
    }
    float m = (0 < out_len[b]) ? mel[(b * DEC_T) * NDIM + tid] : 0.0f;
    g_q[b][tid] = m;   // q_0 = masked mel_0 + ctx_{-1}(=0)
}

// ---------- persistent attention scan ----------
__global__ void __launch_bounds__(NTHR, 1)
attn_persist(const float* __restrict__ enc,
             const float* __restrict__ mel,
             const int*   __restrict__ out_len,
             const float* __restrict__ w_lin,
             const float* __restrict__ w_conv,
             float* __restrict__ att_out,
             float* __restrict__ att_sc) {
    extern __shared__ float sm[];
    float* w_s      = sm + SM_W;
    float* wl_s     = sm + SM_WL;
    float* q_s      = sm + SM_Q;
    float* stage_sc = sm + SM_SSC;
    float* stage_cu = sm + SM_SCU;
    float* red      = sm + SM_RED;
    float* score_s  = sm + SM_SCORE;
    float* wred     = sm + SM_WRED;

    const int tid  = threadIdx.x;
    const int b    = blockIdx.x >> 3;     // batch (same meaning both phases)
    const int sub  = blockIdx.x & 7;      // t-tile (phase A) / d-slice (phase B)
    const int t0   = sub << 6;
    const int warp = tid >> 5, lane = tid & 31;
    const int dg   = warp >> 1;                         // 0..7: 64-d group
    const int t_rel = ((warp & 1) << 5) | lane;         // 0..63 within tile
    const int ol   = out_len[b];

    // Load conv weights into smem ONCE: row d = [w0[0..30], 0, w1[0..30], 0]
    for (int i = tid; i < NDIM * 64; i += NTHR) {
        int d = i >> 6, c = i & 63;
        float v = 0.0f;
        if (c < 31)                 v = w_conv[d * 62 + c];
        else if (c >= 32 && c < 63) v = w_conv[d * 62 + 31 + (c - 32)];
        w_s[i] = v;
    }
    wl_s[tid] = w_lin[tid];
    __syncthreads();

    unsigned bar_target = 0;

    for (int s = 0; s < DEC_T; ++s) {
        // ================= phase A: logits[b, t0..t0+63] =================
        if (tid < 94)                        stage_sc[tid]       = __ldcg(&g_score_pad[b][t0 + tid]);
        else if (tid >= 128 && tid < 222)    stage_cu[tid - 128] = __ldcg(&g_cum_pad[b][t0 + tid - 128]);
        q_s[tid] = __ldcg(&g_q[b][tid]);
        __syncthreads();

        u64 wsc[16], wcu[16];
#pragma unroll
        for (int i = 0; i < 15; ++i) {
            wsc[i] = pack2(stage_sc[t_rel + 2*i], stage_sc[t_rel + 2*i + 1]);
            wcu[i] = pack2(stage_cu[t_rel + 2*i], stage_cu[t_rel + 2*i + 1]);
        }
        wsc[15] = pack2(stage_sc[t_rel + 30], 0.0f);
        wcu[15] = pack2(stage_cu[t_rel + 30], 0.0f);

        float lacc = 0.0f;
        const int dbase = dg << 6;
#pragma unroll 2
        for (int dd = 0; dd < 64; ++dd) {
            const int d = dbase + dd;
            const ulonglong2* wr = reinterpret_cast<const ulonglong2*>(w_s + (d << 6));
            u64 a0 = pack2(q_s[d], 0.0f);   // fold q into the accumulator
            u64 a1 = 0ull;
#pragma unroll
            for (int i = 0; i < 8; ++i) {
                ulonglong2 wv = wr[i];
                a0 = ffma2(wv.x, wsc[2*i],     a0);
                a1 = ffma2(wv.y, wsc[2*i + 1], a1);
            }
#pragma unroll
            for (int i = 0; i < 8; ++i) {
                ulonglong2 wv = wr[8 + i];
                a0 = ffma2(wv.x, wcu[2*i],     a0);
                a1 = ffma2(wv.y, wcu[2*i + 1], a1);
            }
            float x0, x1;
            unpack2(fadd2(a0, a1), x0, x1);
            float pre = x0 + x1;
            lacc = fmaf(wl_s[d], fast_tanh(pre), lacc);
        }
        red[(dg << 6) + t_rel] = lacc;
        __syncthreads();
        if (tid < 64) {
            float v = red[tid];
#pragma unroll
            for (int g = 1; g < 8; ++g) v += red[(g << 6) + tid];
            __stcg(&g_logits[b][t0 + tid], v);
        }
        grid_barrier(bar_target);

        // ======== phase B: softmax + ctx slice + state update ========
        float lv = __ldcg(&g_logits[b][tid]);

        // block max
        float m = lv;
#pragma unroll
        for (int o = 16; o; o >>= 1) m = fmaxf(m, __shfl_xor_sync(0xffffffffu, m, o));
        if (lane == 0) wred[warp] = m;
        __syncthreads();
        if (tid == 0) {
            float mm = wred[0];
#pragma unroll
            for (int i = 1; i < 16; ++i) mm = fmaxf(mm, wred[i]);
            wred[16] = mm;
        }
        __syncthreads();
        const float mx = wred[16];
        float e = __expf(lv - mx);
        float ssum = e;
#pragma unroll
        for (int o = 16; o; o >>= 1) ssum += __shfl_xor_sync(0xffffffffu, ssum, o);
        if (lane == 0) wred[warp] = ssum;
        __syncthreads();
        if (tid == 0) {
            float t = 0.0f;
#pragma unroll
            for (int i = 0; i < 16; ++i) t += wred[i];
            wred[17] = 1.0f / t;
        }
        __syncthreads();
        const float sc = e * wred[17];
        score_s[tid] = sc;
        __syncthreads();

        // ctx[b, d-slice] = sum_t score[t] * enc[b,t,d]
        {
            const int dl = tid & 63, tc = tid >> 6;   // 8 t-chunks of 64
            const float* ep = enc + ((size_t)((b << 9) + (tc << 6)) * NDIM) + (sub << 6) + dl;
            float acc = 0.0f;
#pragma unroll 8
            for (int j = 0; j < 64; ++j)
                acc = fmaf(score_s[(tc << 6) + j], ep[(size_t)j << 9], acc);
            red[tid] = acc;
        }
        __syncthreads();
        if (tid < 64) {
            float c = red[tid];
#pragma unroll
            for (int g = 1; g < 8; ++g) c += red[(g << 6) + tid];
            const int d    = (sub << 6) + tid;
            const int rowo = (b << 10) + s;           // b*DEC_T + s
            att_out[rowo * NDIM + d] = (s < ol) ? c : 0.0f;
            if (s + 1 < DEC_T) {
                float mm2 = (s + 1 < ol) ? mel[(rowo + 1) * NDIM + d] : 0.0f;
                __stcg(&g_q[b][d], mm2 + c);          // q_{s+1} = masked mel + ctx_s
            }
        }
        if (sub == 0) {
            const int rowo = (b << 10) + s;
            const float sv = score_s[tid];
            att_sc[rowo * ENC_T + tid] = sv;
            __stcg(&g_score_pad[b][PADW + tid], sv);
            float oc = __ldcg(&g_cum_pad[b][PADW + tid]);
            __stcg(&g_cum_pad[b][PADW + tid], oc + sv);
        }
        grid_barrier(bar_target);
    }
}

extern "C" void kernel_launch(void* const* d_in, const int* in_sizes, int n_in,
                              void* d_out, int out_size) {
    const float* enc     = (const float*)d_in[0];   // [16,512,512]
    const float* mel     = (const float*)d_in[1];   // [16,1024,512]
    const int*   out_len = (const int*)  d_in[3];   // [16]
    const float* wlin    = (const float*)d_in[4];   // [1,512]
    const float* wconv   = (const float*)d_in[5];   // [512,2,31]
    float* att_out = (float*)d_out;                      // [16,1024,512]
    float* att_sc  = att_out + (size_t)NB * DEC_T * NDIM; // [16,1024,512]

    cudaFuncSetAttribute(attn_persist,
                         cudaFuncAttributeMaxDynamicSharedMemorySize, SM_BYTES);

    attn_init<<<NB, NTHR>>>(mel, out_len);
    attn_persist<<<NCTAS, NTHR, SM_BYTES>>>(enc, mel, out_len, wlin, wconv,
                                            att_out, att_sc);
}

// round 4
// speedup vs baseline: 1.3812x; 1.3812x over previous
#include <cuda_runtime.h>
#include <cuda_bf16.h>

#define NB     16
#define ENC_T  512
#define DEC_T  1024
#define NDIM   512
#define NCTAS  128
#define NTHR   512
#define PADZ   16          // leading zeros in local score/cum pads
#define PADTOT 552         // 16 + 512 + 24 tail zeros

typedef unsigned long long u64;

// ---------- packed f32x2 helpers ----------
__device__ __forceinline__ u64 pack2(float x, float y) {
    u64 r;
    asm("mov.b64 %0, {%1, %2};" : "=l"(r)
        : "r"(__float_as_uint(x)), "r"(__float_as_uint(y)));
    return r;
}
__device__ __forceinline__ void unpack2(u64 v, float& x, float& y) {
    unsigned a, b;
    asm("mov.b64 {%0, %1}, %2;" : "=r"(a), "=r"(b) : "l"(v));
    x = __uint_as_float(a); y = __uint_as_float(b);
}
__device__ __forceinline__ u64 ffma2(u64 a, u64 b, u64 c) {
    u64 d;
    asm("fma.rn.f32x2 %0, %1, %2, %3;" : "=l"(d) : "l"(a), "l"(b), "l"(c));
    return d;
}
__device__ __forceinline__ u64 fadd2(u64 a, u64 b) {
    u64 d;
    asm("add.rn.f32x2 %0, %1, %2;" : "=l"(d) : "l"(a), "l"(b));
    return d;
}

// ---------- persistent globals (no cudaMalloc allowed) ----------
__device__ float    g_lpart[2][NB][8][ENC_T];   // double-buffered logit partials
__device__ unsigned g_bar_count = 0;

// ---------- grid barrier ----------
__device__ __forceinline__ void grid_barrier(unsigned& target) {
    __syncthreads();
    if (threadIdx.x == 0) {
        __threadfence();
        target += (unsigned)NCTAS;
        atomicAdd(&g_bar_count, 1u);
        unsigned cur;
        for (;;) {
            asm volatile("ld.acquire.gpu.u32 %0, [%1];"
                         : "=r"(cur) : "l"(&g_bar_count));
            if ((int)(cur - target) >= 0) break;
            __nanosleep(64);
        }
    }
    __syncthreads();
}

__device__ __forceinline__ float fast_tanh(float x) {
    float e = __expf(x + x);
    return 1.0f - __fdividef(2.0f, e + 1.0f);
}

__global__ void attn_init() {
    g_bar_count = 0;
}

// ---------- persistent attention scan: CTA = (batch, 64-d slice) ----------
__global__ void __launch_bounds__(NTHR, 1)
attn_persist(const float* __restrict__ enc,
             const float* __restrict__ mel,
             const int*   __restrict__ out_len,
             const float* __restrict__ w_lin,
             const float* __restrict__ w_conv,
             float* __restrict__ att_out,
             float* __restrict__ att_sc) {
    extern __shared__ char smraw[];
    ulonglong2* w2     = (ulonglong2*)smraw;            // 64 d rows x 32 ulonglong2 = 32KB
    float*      wl_s   = (float*)(smraw + 32768);       // 64
    float*      q_s    = wl_s + 64;                     // 64
    float*      spad   = q_s + 64;                      // 552 (score, PADZ offset)
    float*      cpad   = spad + PADTOT;                 // 552 (cum)
    float*      score_s= cpad + PADTOT;                 // 512
    float*      red    = score_s + 512;                 // 2048
    float*      wred   = red + 2048;                    // 24

    const int tid  = threadIdx.x;
    const int b    = blockIdx.x >> 3;
    const int sub  = blockIdx.x & 7;
    const int d0   = sub << 6;
    const int warp = tid >> 5, lane = tid & 31;
    const int dg   = warp >> 2;                    // 0..3: 16-d group
    const int tslot = ((warp & 3) << 5) | lane;    // 0..127 -> t0 = 4*tslot
    const int t0   = tslot << 2;
    const int ol   = out_len[b];

    // ---- weight prep: per d, pairs A_i=(shifted,normal) for w0 then w1 ----
    // A.x = (w[2i-1], w[2i])   -> used for t0 and t0+2
    // A.y = (w[2i],   w[2i+1]) -> used for t0+1 and t0+3
    for (int e = tid; e < 64 * 32; e += NTHR) {
        int d = e >> 5, j = e & 31, i = j & 15;
        const float* wb = w_conv + (size_t)(d0 + d) * 62 + ((j < 16) ? 0 : 31);
        float wm1 = (i > 0)  ? wb[2*i - 1] : 0.0f;
        float w0v = wb[2*i];
        float wp1 = (i < 15) ? wb[2*i + 1] : 0.0f;
        ulonglong2 v;
        v.x = pack2(wm1, w0v);
        v.y = pack2(w0v, wp1);
        w2[(d << 5) + j] = v;
    }
    if (tid < 64) {
        wl_s[tid] = w_lin[d0 + tid];
        q_s[tid]  = (0 < ol) ? mel[(size_t)(b * DEC_T) * NDIM + d0 + tid] : 0.0f;
    }
    for (int i = tid; i < PADTOT; i += NTHR) { spad[i] = 0.0f; cpad[i] = 0.0f; }
    __syncthreads();

    unsigned bar_target = 0;

    for (int s = 0; s < DEC_T; ++s) {
        const int par = s & 1;

        // ============ phase A: partial logits over local 64 d, all 512 t ============
        // windows: V[m] = pad[t0 + m], m=0..35 ; W[i] = (V[2i], V[2i+1])
        u64 Ws[18], Wc[18];
        {
            const float4* sp4 = reinterpret_cast<const float4*>(spad + t0);
            const float4* cp4 = reinterpret_cast<const float4*>(cpad + t0);
#pragma unroll
            for (int j = 0; j < 9; ++j) {
                float4 f = sp4[j];
                Ws[2*j]   = pack2(f.x, f.y);
                Ws[2*j+1] = pack2(f.z, f.w);
                float4 g = cp4[j];
                Wc[2*j]   = pack2(g.x, g.y);
                Wc[2*j+1] = pack2(g.z, g.w);
            }
        }

        float lacc0 = 0.f, lacc1 = 0.f, lacc2 = 0.f, lacc3 = 0.f;
        const ulonglong2* wrow = w2 + ((dg * 16) << 5);
#pragma unroll 2
        for (int dd = 0; dd < 16; ++dd) {
            const ulonglong2* wr = wrow + (dd << 5);
            u64 as0 = 0, as1 = 0, as2 = 0, as3 = 0;
            u64 ac0 = 0, ac1 = 0, ac2 = 0, ac3 = 0;
#pragma unroll
            for (int i = 0; i < 16; ++i) {
                ulonglong2 A = wr[i];
                as0 = ffma2(A.x, Ws[i],     as0);
                as1 = ffma2(A.y, Ws[i + 1], as1);
                as2 = ffma2(A.x, Ws[i + 1], as2);
                as3 = ffma2(A.y, Ws[i + 2], as3);
            }
#pragma unroll
            for (int i = 0; i < 16; ++i) {
                ulonglong2 Bv = wr[16 + i];
                ac0 = ffma2(Bv.x, Wc[i],     ac0);
                ac1 = ffma2(Bv.y, Wc[i + 1], ac1);
                ac2 = ffma2(Bv.x, Wc[i + 1], ac2);
                ac3 = ffma2(Bv.y, Wc[i + 2], ac3);
            }
            const int d = dg * 16 + dd;
            const float qd = q_s[d], wld = wl_s[d];
            float x, y, pre;
            unpack2(fadd2(as0, ac0), x, y); pre = qd + x + y;
            lacc0 = fmaf(wld, fast_tanh(pre), lacc0);
            unpack2(fadd2(as1, ac1), x, y); pre = qd + x + y;
            lacc1 = fmaf(wld, fast_tanh(pre), lacc1);
            unpack2(fadd2(as2, ac2), x, y); pre = qd + x + y;
            lacc2 = fmaf(wld, fast_tanh(pre), lacc2);
            unpack2(fadd2(as3, ac3), x, y); pre = qd + x + y;
            lacc3 = fmaf(wld, fast_tanh(pre), lacc3);
        }
        reinterpret_cast<float4*>(red + (dg << 9) + t0)[0] =
            make_float4(lacc0, lacc1, lacc2, lacc3);
        __syncthreads();

        {   // reduce the 4 d-groups, publish partial logits
            float lp = red[tid] + red[512 + tid] + red[1024 + tid] + red[1536 + tid];
            __stcg(&g_lpart[par][b][sub][tid], lp);
        }
        grid_barrier(bar_target);

        // ============ phase B: full logits -> softmax -> ctx slice -> q ============
        float lv = 0.0f;
#pragma unroll
        for (int j = 0; j < 8; ++j)
            lv += __ldcg(&g_lpart[par][b][j][tid]);

        // block max
        float m = lv;
#pragma unroll
        for (int o = 16; o; o >>= 1) m = fmaxf(m, __shfl_xor_sync(0xffffffffu, m, o));
        if (lane == 0) wred[warp] = m;
        __syncthreads();
        if (tid == 0) {
            float mm = wred[0];
#pragma unroll
            for (int i = 1; i < 16; ++i) mm = fmaxf(mm, wred[i]);
            wred[16] = mm;
        }
        __syncthreads();
        const float mx = wred[16];
        float e = __expf(lv - mx);
        float ssum = e;
#pragma unroll
        for (int o = 16; o; o >>= 1) ssum += __shfl_xor_sync(0xffffffffu, ssum, o);
        if (lane == 0) wred[warp] = ssum;
        __syncthreads();
        if (tid == 0) {
            float t = 0.0f;
#pragma unroll
            for (int i = 0; i < 16; ++i) t += wred[i];
            wred[17] = 1.0f / t;
        }
        __syncthreads();
        const float sc = e * wred[17];
        score_s[tid]        = sc;
        spad[PADZ + tid]    = sc;
        cpad[PADZ + tid]   += sc;
        __syncthreads();

        // ctx[b, d-slice] = sum_t score[t] * enc[b,t,d0+dl]
        {
            const int dl = tid & 63, tc = tid >> 6;
            const float* ep = enc + ((size_t)(b * ENC_T + (tc << 6)) * NDIM) + d0 + dl;
            float acc = 0.0f;
#pragma unroll 8
            for (int j = 0; j < 64; ++j)
                acc = fmaf(score_s[(tc << 6) + j], ep[(size_t)j * NDIM], acc);
            red[tid] = acc;
        }
        __syncthreads();
        const int rowo = (b << 10) + s;
        if (tid < 64) {
            float c = red[tid];
#pragma unroll
            for (int g = 1; g < 8; ++g) c += red[(g << 6) + tid];
            const int d = d0 + tid;
            att_out[(size_t)rowo * NDIM + d] = (s < ol) ? c : 0.0f;
            float mm2 = 0.0f;
            if (s + 1 < ol)  // implies s+1 < DEC_T+1; guard mel read
                mm2 = (s + 1 < DEC_T) ? mel[(size_t)(rowo + 1) * NDIM + d] : 0.0f;
            q_s[tid] = c + mm2;
        }
        if (sub == 0)
            att_sc[(size_t)rowo * ENC_T + tid] = sc;
        __syncthreads();   // q_s/spad/cpad ready for next phase A
    }
}

extern "C" void kernel_launch(void* const* d_in, const int* in_sizes, int n_in,
                              void* d_out, int out_size) {
    const float* enc     = (const float*)d_in[0];   // [16,512,512]
    const float* mel     = (const float*)d_in[1];   // [16,1024,512]
    const int*   out_len = (const int*)  d_in[3];   // [16]
    const float* wlin    = (const float*)d_in[4];   // [1,512]
    const float* wconv   = (const float*)d_in[5];   // [512,2,31]
    float* att_out = (float*)d_out;                                // [16,1024,512]
    float* att_sc  = att_out + (size_t)NB * DEC_T * NDIM;          // [16,1024,512]

    const int smem_bytes = 32768 + (64 + 64 + PADTOT * 2 + 512 + 2048 + 24) * 4;
    cudaFuncSetAttribute(attn_persist,
                         cudaFuncAttributeMaxDynamicSharedMemorySize, smem_bytes);

    attn_init<<<1, 1>>>();
    attn_persist<<<NCTAS, NTHR, smem_bytes>>>(enc, mel, out_len, wlin, wconv,
                                              att_out, att_sc);
}

// round 5
// speedup vs baseline: 1.4820x; 1.0730x over previous
#include <cuda_runtime.h>
#include <cuda_bf16.h>

#define NB     16
#define ENC_T  512
#define DEC_T  1024
#define NDIM   512
#define NCTAS  128
#define NTHR   512
#define PADZ   16
#define PADTOT 544          // 16 zeros + 512 scores + 16 zero tail

typedef unsigned long long u64;

// smem layout (bytes), all 16B aligned
#define OFF_W    0            // 32768  : weights, 64 d x 32 ulonglong2
#define OFF_CC   32768        // 131072 : CC[64][512] = conv1(cum)
#define OFF_RED  163840       // 16384  : red[8][512]
#define OFF_SPAD 180224       // 2176   : padded score window
#define OFF_SC   182400       // 2048   : score
#define OFF_Q    184448       // 256    : q slice
#define OFF_WL   184704       // 256    : w_lin slice
#define OFF_WRED 184960       // 128
#define SM_BYTES 185088

__device__ __forceinline__ u64 pack2(float x, float y) {
    u64 r;
    asm("mov.b64 %0, {%1, %2};" : "=l"(r)
        : "r"(__float_as_uint(x)), "r"(__float_as_uint(y)));
    return r;
}
__device__ __forceinline__ void unpack2(u64 v, float& x, float& y) {
    unsigned a, b;
    asm("mov.b64 {%0, %1}, %2;" : "=r"(a), "=r"(b) : "l"(v));
    x = __uint_as_float(a); y = __uint_as_float(b);
}
__device__ __forceinline__ u64 ffma2(u64 a, u64 b, u64 c) {
    u64 d;
    asm("fma.rn.f32x2 %0, %1, %2, %3;" : "=l"(d) : "l"(a), "l"(b), "l"(c));
    return d;
}

// ---------- persistent globals ----------
__device__ float    g_lpart[2][NB][8][ENC_T];
__device__ unsigned g_bar[NB];

__global__ void attn_init() {
    if (threadIdx.x < NB) g_bar[threadIdx.x] = 0;
}

__device__ __forceinline__ float fast_tanh(float x) {
    float e = __expf(x + x);
    return 1.0f - __fdividef(2.0f, e + 1.0f);
}

// hsum of a u64 f32x2
__device__ __forceinline__ float hsum2(u64 v) {
    float x, y; unpack2(v, x, y); return x + y;
}

__global__ void __launch_bounds__(NTHR, 1)
attn_persist(const float* __restrict__ enc,
             const float* __restrict__ mel,
             const int*   __restrict__ out_len,
             const float* __restrict__ w_lin,
             const float* __restrict__ w_conv,
             float* __restrict__ att_out,
             float* __restrict__ att_sc) {
    extern __shared__ char smraw[];
    ulonglong2* w2      = (ulonglong2*)(smraw + OFF_W);
    float*      cc_s    = (float*)(smraw + OFF_CC);
    float*      red     = (float*)(smraw + OFF_RED);
    float*      spad    = (float*)(smraw + OFF_SPAD);
    float*      score_s = (float*)(smraw + OFF_SC);
    float*      q_s     = (float*)(smraw + OFF_Q);
    float*      wl_s    = (float*)(smraw + OFF_WL);
    float*      wred    = (float*)(smraw + OFF_WRED);

    const int tid  = threadIdx.x;
    const int b    = blockIdx.x >> 3;
    const int sub  = blockIdx.x & 7;
    const int d0   = sub << 6;
    const int warp = tid >> 5, lane = tid & 31;
    const int dg   = warp >> 1;                       // 0..7 : 8-d group
    const int tslot = ((warp & 1) << 5) | lane;       // 0..63
    const int t0   = tslot << 3;                      // 8 t per thread
    const int ol   = out_len[b];

    // weights: per local d, 16 pairs for w0 then 16 for w1
    // A.x = (w[2i-1], w[2i]),  A.y = (w[2i], w[2i+1]), zero-padded edges
    for (int e = tid; e < 64 * 32; e += NTHR) {
        int d = e >> 5, j = e & 31, i = j & 15;
        const float* wb = w_conv + (size_t)(d0 + d) * 62 + ((j < 16) ? 0 : 31);
        float wm1 = (i > 0)  ? wb[2*i - 1] : 0.0f;
        float w0v = wb[2*i];
        float wp1 = (i < 15) ? wb[2*i + 1] : 0.0f;
        ulonglong2 v;
        v.x = pack2(wm1, w0v);
        v.y = pack2(w0v, wp1);
        w2[(d << 5) + j] = v;
    }
    if (tid < 64) {
        wl_s[tid] = w_lin[d0 + tid];
        q_s[tid]  = (0 < ol) ? mel[(size_t)(b * DEC_T) * NDIM + d0 + tid] : 0.0f;
    }
    for (int i = tid; i < PADTOT; i += NTHR) spad[i] = 0.0f;
    for (int i = tid; i < 64 * 512; i += NTHR) cc_s[i] = 0.0f;
    __syncthreads();

    unsigned bar_target = 0;

    for (int s = 0; s < DEC_T; ++s) {
        const int par = s & 1;

        // ===== phase A: window of score_{s-1}, conv0 + incremental conv1 =====
        u64 Ws[20];
        {
            const float4* sp4 = reinterpret_cast<const float4*>(spad + t0);
#pragma unroll
            for (int j = 0; j < 10; ++j) {
                float4 f = sp4[j];
                Ws[2*j]   = pack2(f.x, f.y);
                Ws[2*j+1] = pack2(f.z, f.w);
            }
        }

        float lacc0=0.f,lacc1=0.f,lacc2=0.f,lacc3=0.f;
        float lacc4=0.f,lacc5=0.f,lacc6=0.f,lacc7=0.f;

#pragma unroll 1
        for (int dd = 0; dd < 8; ++dd) {
            const int d = (dg << 3) + dd;
            float* ccp = cc_s + (d << 9) + t0;
            float4 cc0 = reinterpret_cast<float4*>(ccp)[0];
            float4 cc1 = reinterpret_cast<float4*>(ccp)[1];
            const ulonglong2* wr = w2 + (d << 5);

            u64 as0=0,as1=0,as2=0,as3=0,as4=0,as5=0,as6=0,as7=0;
            u64 av0=0,av1=0,av2=0,av3=0,av4=0,av5=0,av6=0,av7=0;
#pragma unroll
            for (int i = 0; i < 16; ++i) {
                ulonglong2 A  = wr[i];
                ulonglong2 Bv = wr[16 + i];
                as0 = ffma2(A.x,  Ws[i],     as0);
                as1 = ffma2(A.y,  Ws[i + 1], as1);
                as2 = ffma2(A.x,  Ws[i + 1], as2);
                as3 = ffma2(A.y,  Ws[i + 2], as3);
                as4 = ffma2(A.x,  Ws[i + 2], as4);
                as5 = ffma2(A.y,  Ws[i + 3], as5);
                as6 = ffma2(A.x,  Ws[i + 3], as6);
                as7 = ffma2(A.y,  Ws[i + 4], as7);
                av0 = ffma2(Bv.x, Ws[i],     av0);
                av1 = ffma2(Bv.y, Ws[i + 1], av1);
                av2 = ffma2(Bv.x, Ws[i + 1], av2);
                av3 = ffma2(Bv.y, Ws[i + 2], av3);
                av4 = ffma2(Bv.x, Ws[i + 2], av4);
                av5 = ffma2(Bv.y, Ws[i + 3], av5);
                av6 = ffma2(Bv.x, Ws[i + 3], av6);
                av7 = ffma2(Bv.y, Ws[i + 4], av7);
            }
            const float qd = q_s[d], wld = wl_s[d];

            float c0 = cc0.x + hsum2(av0);
            float c1 = cc0.y + hsum2(av1);
            float c2 = cc0.z + hsum2(av2);
            float c3 = cc0.w + hsum2(av3);
            float c4 = cc1.x + hsum2(av4);
            float c5 = cc1.y + hsum2(av5);
            float c6 = cc1.z + hsum2(av6);
            float c7 = cc1.w + hsum2(av7);
            reinterpret_cast<float4*>(ccp)[0] = make_float4(c0, c1, c2, c3);
            reinterpret_cast<float4*>(ccp)[1] = make_float4(c4, c5, c6, c7);

            lacc0 = fmaf(wld, fast_tanh(qd + hsum2(as0) + c0), lacc0);
            lacc1 = fmaf(wld, fast_tanh(qd + hsum2(as1) + c1), lacc1);
            lacc2 = fmaf(wld, fast_tanh(qd + hsum2(as2) + c2), lacc2);
            lacc3 = fmaf(wld, fast_tanh(qd + hsum2(as3) + c3), lacc3);
            lacc4 = fmaf(wld, fast_tanh(qd + hsum2(as4) + c4), lacc4);
            lacc5 = fmaf(wld, fast_tanh(qd + hsum2(as5) + c5), lacc5);
            lacc6 = fmaf(wld, fast_tanh(qd + hsum2(as6) + c6), lacc6);
            lacc7 = fmaf(wld, fast_tanh(qd + hsum2(as7) + c7), lacc7);
        }
        {
            float* rp = red + (dg << 9) + t0;
            reinterpret_cast<float4*>(rp)[0] = make_float4(lacc0, lacc1, lacc2, lacc3);
            reinterpret_cast<float4*>(rp)[1] = make_float4(lacc4, lacc5, lacc6, lacc7);
        }
        __syncthreads();
        {
            float lp = 0.0f;
#pragma unroll
            for (int g = 0; g < 8; ++g) lp += red[(g << 9) + tid];
            __stcg(&g_lpart[par][b][sub][tid], lp);
        }

        // ===== per-batch barrier =====
        __syncthreads();
        if (tid == 0) {
            __threadfence();
            bar_target += 8u;
            atomicAdd(&g_bar[b], 1u);
            unsigned cur;
            for (;;) {
                asm volatile("ld.acquire.gpu.u32 %0, [%1];"
                             : "=r"(cur) : "l"(&g_bar[b]));
                if ((int)(cur - bar_target) >= 0) break;
                __nanosleep(32);
            }
        }
        __syncthreads();

        // ===== phase B: softmax (no max pass; |logit| <= ~18), ctx, q =====
        float lv = 0.0f;
#pragma unroll
        for (int j = 0; j < 8; ++j)
            lv += __ldcg(&g_lpart[par][b][j][tid]);

        const float e = __expf(lv);
        float ssum = e;
#pragma unroll
        for (int o = 16; o; o >>= 1) ssum += __shfl_xor_sync(0xffffffffu, ssum, o);
        if (lane == 0) wred[warp] = ssum;
        __syncthreads();
        if (warp == 0) {
            float v = (lane < 16) ? wred[lane] : 0.0f;
#pragma unroll
            for (int o = 8; o; o >>= 1) v += __shfl_xor_sync(0xffffffffu, v, o);
            if (lane == 0) wred[16] = __fdividef(1.0f, v);
        }
        __syncthreads();
        const float sc = e * wred[16];
        score_s[tid]     = sc;
        spad[PADZ + tid] = sc;
        __syncthreads();

        // ctx[b, d-slice]
        {
            const int dl = tid & 63, tc = tid >> 6;
            const float* ep = enc + ((size_t)(b * ENC_T + (tc << 6)) * NDIM) + d0 + dl;
            const float* sp = score_s + (tc << 6);
            float a0 = 0.f, a1 = 0.f, a2 = 0.f, a3 = 0.f;
#pragma unroll 4
            for (int j = 0; j < 64; j += 4) {
                a0 = fmaf(sp[j],     ep[(size_t)(j)     * NDIM], a0);
                a1 = fmaf(sp[j + 1], ep[(size_t)(j + 1) * NDIM], a1);
                a2 = fmaf(sp[j + 2], ep[(size_t)(j + 2) * NDIM], a2);
                a3 = fmaf(sp[j + 3], ep[(size_t)(j + 3) * NDIM], a3);
            }
            red[tid] = (a0 + a1) + (a2 + a3);
        }
        __syncthreads();
        const int rowo = (b << 10) + s;
        if (tid < 64) {
            float c = red[tid];
#pragma unroll
            for (int g = 1; g < 8; ++g) c += red[(g << 6) + tid];
            const int d = d0 + tid;
            att_out[(size_t)rowo * NDIM + d] = (s < ol) ? c : 0.0f;
            float mm2 = 0.0f;
            if (s + 1 < ol)
                mm2 = (s + 1 < DEC_T) ? mel[(size_t)(rowo + 1) * NDIM + d] : 0.0f;
            q_s[tid] = c + mm2;
        }
        if (sub == 0)
            att_sc[(size_t)rowo * ENC_T + tid] = sc;
        __syncthreads();
    }
}

extern "C" void kernel_launch(void* const* d_in, const int* in_sizes, int n_in,
                              void* d_out, int out_size) {
    const float* enc     = (const float*)d_in[0];
    const float* mel     = (const float*)d_in[1];
    const int*   out_len = (const int*)  d_in[3];
    const float* wlin    = (const float*)d_in[4];
    const float* wconv   = (const float*)d_in[5];
    float* att_out = (float*)d_out;
    float* att_sc  = att_out + (size_t)NB * DEC_T * NDIM;

    cudaFuncSetAttribute(attn_persist,
                         cudaFuncAttributeMaxDynamicSharedMemorySize, SM_BYTES);

    attn_init<<<1, 32>>>();
    attn_persist<<<NCTAS, NTHR, SM_BYTES>>>(enc, mel, out_len, wlin, wconv,
                                            att_out, att_sc);
}

// round 6
// speedup vs baseline: 1.5594x; 1.0522x over previous
#include <cuda_runtime.h>
#include <cuda_bf16.h>

#define NB     16
#define ENC_T  512
#define DEC_T  1024
#define NDIM   512
#define NSUB   16          // 16 d-slices of 32
#define NCTAS  (NB * NSUB) // 256
#define NTHR   256
#define PADZ   16
#define PADTOT 544

typedef unsigned long long u64;

// smem layout (bytes per CTA)
#define OFF_W    0            // 16384 : 32 d x 32 ulonglong2
#define OFF_CC   16384        // 65536 : CC[32][512]
#define OFF_RED  81920        // 8192  : red[4][512]
#define OFF_SPAD 90112        // 2176
#define OFF_SC   92288        // 2048
#define OFF_Q    94336        // 128
#define OFF_WL   94464        // 128
#define OFF_WRED 94592        // 64
#define SM_BYTES 94656

__device__ __forceinline__ u64 pack2(float x, float y) {
    u64 r;
    asm("mov.b64 %0, {%1, %2};" : "=l"(r)
        : "r"(__float_as_uint(x)), "r"(__float_as_uint(y)));
    return r;
}
__device__ __forceinline__ void unpack2(u64 v, float& x, float& y) {
    unsigned a, b;
    asm("mov.b64 {%0, %1}, %2;" : "=r"(a), "=r"(b) : "l"(v));
    x = __uint_as_float(a); y = __uint_as_float(b);
}
__device__ __forceinline__ u64 ffma2(u64 a, u64 b, u64 c) {
    u64 d;
    asm("fma.rn.f32x2 %0, %1, %2, %3;" : "=l"(d) : "l"(a), "l"(b), "l"(c));
    return d;
}
__device__ __forceinline__ float hsum2(u64 v) {
    float x, y; unpack2(v, x, y); return x + y;
}
__device__ __forceinline__ float fast_tanh(float x) {
    float e = __expf(x + x);
    return 1.0f - __fdividef(2.0f, e + 1.0f);
}

// ---------- persistent globals ----------
__device__ float    g_lpart[2][NB][NSUB][ENC_T];
__device__ unsigned g_bar[NB];

__global__ void attn_init() {
    if (threadIdx.x < NB) g_bar[threadIdx.x] = 0;
}

__global__ void __launch_bounds__(NTHR, 2)
attn_persist(const float* __restrict__ enc,
             const float* __restrict__ mel,
             const int*   __restrict__ out_len,
             const float* __restrict__ w_lin,
             const float* __restrict__ w_conv,
             float* __restrict__ att_out,
             float* __restrict__ att_sc) {
    extern __shared__ char smraw[];
    ulonglong2* w2      = (ulonglong2*)(smraw + OFF_W);
    float*      cc_s    = (float*)(smraw + OFF_CC);
    float*      red     = (float*)(smraw + OFF_RED);
    float*      spad    = (float*)(smraw + OFF_SPAD);
    float*      score_s = (float*)(smraw + OFF_SC);
    float*      q_s     = (float*)(smraw + OFF_Q);
    float*      wl_s    = (float*)(smraw + OFF_WL);
    float*      wred    = (float*)(smraw + OFF_WRED);

    const int tid  = threadIdx.x;
    const int b    = blockIdx.x >> 4;       // batch
    const int sub  = blockIdx.x & 15;       // 32-d slice
    const int d0   = sub << 5;
    const int warp = tid >> 5, lane = tid & 31;
    const int dg   = warp >> 1;                       // 0..3 : 8-d group
    const int tslot = ((warp & 1) << 5) | lane;       // 0..63
    const int t0   = tslot << 3;                      // 8 t per thread
    const int ol   = out_len[b];

    // weights: per local d (32), 16 pairs for w0 then 16 for w1
    for (int e = tid; e < 32 * 32; e += NTHR) {
        int d = e >> 5, j = e & 31, i = j & 15;
        const float* wb = w_conv + (size_t)(d0 + d) * 62 + ((j < 16) ? 0 : 31);
        float wm1 = (i > 0)  ? wb[2*i - 1] : 0.0f;
        float w0v = wb[2*i];
        float wp1 = (i < 15) ? wb[2*i + 1] : 0.0f;
        ulonglong2 v;
        v.x = pack2(wm1, w0v);
        v.y = pack2(w0v, wp1);
        w2[(d << 5) + j] = v;
    }
    if (tid < 32) {
        wl_s[tid] = w_lin[d0 + tid];
        q_s[tid]  = (0 < ol) ? mel[(size_t)(b * DEC_T) * NDIM + d0 + tid] : 0.0f;
    }
    for (int i = tid; i < PADTOT; i += NTHR) spad[i] = 0.0f;
    for (int i = tid; i < 32 * 512; i += NTHR) cc_s[i] = 0.0f;
    __syncthreads();

    unsigned bar_target = 0;

    for (int s = 0; s < DEC_T; ++s) {
        const int par = s & 1;

        // ===== phase A: conv0(score) + incremental conv1(cum) over 32 d =====
        u64 Ws[20];
        {
            const float4* sp4 = reinterpret_cast<const float4*>(spad + t0);
#pragma unroll
            for (int j = 0; j < 10; ++j) {
                float4 f = sp4[j];
                Ws[2*j]   = pack2(f.x, f.y);
                Ws[2*j+1] = pack2(f.z, f.w);
            }
        }

        float lacc0=0.f,lacc1=0.f,lacc2=0.f,lacc3=0.f;
        float lacc4=0.f,lacc5=0.f,lacc6=0.f,lacc7=0.f;

#pragma unroll 1
        for (int dd = 0; dd < 8; ++dd) {
            const int d = (dg << 3) + dd;
            float* ccp = cc_s + (d << 9) + t0;
            float4 cc0 = reinterpret_cast<float4*>(ccp)[0];
            float4 cc1 = reinterpret_cast<float4*>(ccp)[1];
            const ulonglong2* wr = w2 + (d << 5);

            u64 as0=0,as1=0,as2=0,as3=0,as4=0,as5=0,as6=0,as7=0;
            u64 av0=0,av1=0,av2=0,av3=0,av4=0,av5=0,av6=0,av7=0;
#pragma unroll
            for (int i = 0; i < 16; ++i) {
                ulonglong2 A  = wr[i];
                ulonglong2 Bv = wr[16 + i];
                as0 = ffma2(A.x,  Ws[i],     as0);
                as1 = ffma2(A.y,  Ws[i + 1], as1);
                as2 = ffma2(A.x,  Ws[i + 1], as2);
                as3 = ffma2(A.y,  Ws[i + 2], as3);
                as4 = ffma2(A.x,  Ws[i + 2], as4);
                as5 = ffma2(A.y,  Ws[i + 3], as5);
                as6 = ffma2(A.x,  Ws[i + 3], as6);
                as7 = ffma2(A.y,  Ws[i + 4], as7);
                av0 = ffma2(Bv.x, Ws[i],     av0);
                av1 = ffma2(Bv.y, Ws[i + 1], av1);
                av2 = ffma2(Bv.x, Ws[i + 1], av2);
                av3 = ffma2(Bv.y, Ws[i + 2], av3);
                av4 = ffma2(Bv.x, Ws[i + 2], av4);
                av5 = ffma2(Bv.y, Ws[i + 3], av5);
                av6 = ffma2(Bv.x, Ws[i + 3], av6);
                av7 = ffma2(Bv.y, Ws[i + 4], av7);
            }
            const float qd = q_s[d], wld = wl_s[d];

            float c0 = cc0.x + hsum2(av0);
            float c1 = cc0.y + hsum2(av1);
            float c2 = cc0.z + hsum2(av2);
            float c3 = cc0.w + hsum2(av3);
            float c4 = cc1.x + hsum2(av4);
            float c5 = cc1.y + hsum2(av5);
            float c6 = cc1.z + hsum2(av6);
            float c7 = cc1.w + hsum2(av7);
            reinterpret_cast<float4*>(ccp)[0] = make_float4(c0, c1, c2, c3);
            reinterpret_cast<float4*>(ccp)[1] = make_float4(c4, c5, c6, c7);

            lacc0 = fmaf(wld, fast_tanh(qd + hsum2(as0) + c0), lacc0);
            lacc1 = fmaf(wld, fast_tanh(qd + hsum2(as1) + c1), lacc1);
            lacc2 = fmaf(wld, fast_tanh(qd + hsum2(as2) + c2), lacc2);
            lacc3 = fmaf(wld, fast_tanh(qd + hsum2(as3) + c3), lacc3);
            lacc4 = fmaf(wld, fast_tanh(qd + hsum2(as4) + c4), lacc4);
            lacc5 = fmaf(wld, fast_tanh(qd + hsum2(as5) + c5), lacc5);
            lacc6 = fmaf(wld, fast_tanh(qd + hsum2(as6) + c6), lacc6);
            lacc7 = fmaf(wld, fast_tanh(qd + hsum2(as7) + c7), lacc7);
        }
        {
            float* rp = red + (dg << 9) + t0;
            reinterpret_cast<float4*>(rp)[0] = make_float4(lacc0, lacc1, lacc2, lacc3);
            reinterpret_cast<float4*>(rp)[1] = make_float4(lacc4, lacc5, lacc6, lacc7);
        }
        __syncthreads();
#pragma unroll
        for (int k = 0; k < 2; ++k) {
            const int t = tid + (k << 8);
            float lp = red[t] + red[512 + t] + red[1024 + t] + red[1536 + t];
            __stcg(&g_lpart[par][b][sub][t], lp);
        }

        // ===== per-batch barrier (release arrive, acquire poll) =====
        __syncthreads();
        if (tid == 0) {
            bar_target += (unsigned)NSUB;
            asm volatile("red.release.gpu.global.add.u32 [%0], %1;"
                         :: "l"(&g_bar[b]), "r"(1u) : "memory");
            unsigned cur;
            for (;;) {
                asm volatile("ld.acquire.gpu.u32 %0, [%1];"
                             : "=r"(cur) : "l"(&g_bar[b]));
                if ((int)(cur - bar_target) >= 0) break;
                __nanosleep(32);
            }
        }
        __syncthreads();

        // ===== phase B: softmax (no max pass; |logit| <= ~18), ctx, q =====
        float lv0 = 0.0f, lv1 = 0.0f;
#pragma unroll
        for (int j = 0; j < NSUB; ++j) {
            lv0 += __ldcg(&g_lpart[par][b][j][tid]);
            lv1 += __ldcg(&g_lpart[par][b][j][tid + 256]);
        }
        const float e0 = __expf(lv0);
        const float e1 = __expf(lv1);
        float ssum = e0 + e1;
#pragma unroll
        for (int o = 16; o; o >>= 1) ssum += __shfl_xor_sync(0xffffffffu, ssum, o);
        if (lane == 0) wred[warp] = ssum;
        __syncthreads();
        if (warp == 0) {
            float v = (lane < 8) ? wred[lane] : 0.0f;
#pragma unroll
            for (int o = 4; o; o >>= 1) v += __shfl_xor_sync(0xffffffffu, v, o);
            if (lane == 0) wred[8] = __fdividef(1.0f, v);
        }
        __syncthreads();
        const float inv = wred[8];
        const float sc0 = e0 * inv, sc1 = e1 * inv;
        score_s[tid]           = sc0;
        score_s[tid + 256]     = sc1;
        spad[PADZ + tid]       = sc0;
        spad[PADZ + tid + 256] = sc1;
        __syncthreads();

        // ctx[b, 32-d slice] = sum_t score[t] * enc[b,t,d0+dl]
        {
            const int dl = tid & 31, tc = tid >> 5;   // 8 chunks of 64 t
            const float* ep = enc + ((size_t)(b * ENC_T + (tc << 6)) * NDIM) + d0 + dl;
            const float* sp = score_s + (tc << 6);
            float a0 = 0.f, a1 = 0.f, a2 = 0.f, a3 = 0.f;
#pragma unroll 4
            for (int j = 0; j < 64; j += 4) {
                a0 = fmaf(sp[j],     ep[(size_t)(j)     * NDIM], a0);
                a1 = fmaf(sp[j + 1], ep[(size_t)(j + 1) * NDIM], a1);
                a2 = fmaf(sp[j + 2], ep[(size_t)(j + 2) * NDIM], a2);
                a3 = fmaf(sp[j + 3], ep[(size_t)(j + 3) * NDIM], a3);
            }
            red[tid] = (a0 + a1) + (a2 + a3);
        }
        __syncthreads();
        const int rowo = (b << 10) + s;
        if (tid < 32) {
            float c = red[tid];
#pragma unroll
            for (int g = 1; g < 8; ++g) c += red[(g << 5) + tid];
            const int d = d0 + tid;
            att_out[(size_t)rowo * NDIM + d] = (s < ol) ? c : 0.0f;
            float mm2 = 0.0f;
            if (s + 1 < ol)
                mm2 = (s + 1 < DEC_T) ? mel[(size_t)(rowo + 1) * NDIM + d] : 0.0f;
            q_s[tid] = c + mm2;
        }
        if (sub == 0) {
            att_sc[(size_t)rowo * ENC_T + tid]       = sc0;
            att_sc[(size_t)rowo * ENC_T + tid + 256] = sc1;
        }
        __syncthreads();
    }
}

extern "C" void kernel_launch(void* const* d_in, const int* in_sizes, int n_in,
                              void* d_out, int out_size) {
    const float* enc     = (const float*)d_in[0];
    const float* mel     = (const float*)d_in[1];
    const int*   out_len = (const int*)  d_in[3];
    const float* wlin    = (const float*)d_in[4];
    const float* wconv   = (const float*)d_in[5];
    float* att_out = (float*)d_out;
    float* att_sc  = att_out + (size_t)NB * DEC_T * NDIM;

    cudaFuncSetAttribute(attn_persist,
                         cudaFuncAttributeMaxDynamicSharedMemorySize, SM_BYTES);

    attn_init<<<1, 32>>>();
    attn_persist<<<NCTAS, NTHR, SM_BYTES>>>(enc, mel, out_len, wlin, wconv,
                                            att_out, att_sc);
}

// round 7
// speedup vs baseline: 1.5597x; 1.0002x over previous
#include <cuda_runtime.h>
#include <cuda_bf16.h>

#define NB     16
#define ENC_T  512
#define DEC_T  1024
#define NDIM   512
#define NSUB   16          // 16 d-slices of 32
#define NCTAS  (NB * NSUB) // 256
#define NTHR   256
#define PADZ   16
#define PADTOT 544

typedef unsigned long long u64;

// smem layout (bytes per CTA)
#define OFF_W    0            // 16384 : 32 d x 32 ulonglong2
#define OFF_CC   16384        // 65536 : CC[32][512]
#define OFF_RED  81920        // 8192  : red[4][512]
#define OFF_SPAD 90112        // 2176
#define OFF_SC   92288        // 2048
#define OFF_Q    94336        // 128
#define OFF_WL   94464        // 128
#define OFF_WRED 94592        // 64
#define SM_BYTES 94656

__device__ __forceinline__ u64 pack2(float x, float y) {
    u64 r;
    asm("mov.b64 %0, {%1, %2};" : "=l"(r)
        : "r"(__float_as_uint(x)), "r"(__float_as_uint(y)));
    return r;
}
__device__ __forceinline__ void unpack2(u64 v, float& x, float& y) {
    unsigned a, b;
    asm("mov.b64 {%0, %1}, %2;" : "=r"(a), "=r"(b) : "l"(v));
    x = __uint_as_float(a); y = __uint_as_float(b);
}
__device__ __forceinline__ u64 ffma2(u64 a, u64 b, u64 c) {
    u64 d;
    asm("fma.rn.f32x2 %0, %1, %2, %3;" : "=l"(d) : "l"(a), "l"(b), "l"(c));
    return d;
}
__device__ __forceinline__ float hsum2(u64 v) {
    float x, y; unpack2(v, x, y); return x + y;
}
__device__ __forceinline__ float fast_tanh(float x) {
    float e = __expf(x + x);
    return 1.0f - __fdividef(2.0f, e + 1.0f);
}

// ---------- persistent globals ----------
__device__ float    g_lpart[2][NB][NSUB][ENC_T];
__device__ unsigned g_bar[NB];

__global__ void attn_init() {
    if (threadIdx.x < NB) g_bar[threadIdx.x] = 0;
}

__global__ void __launch_bounds__(NTHR, 2)
attn_persist(const float* __restrict__ enc,
             const float* __restrict__ mel,
             const int*   __restrict__ out_len,
             const float* __restrict__ w_lin,
             const float* __restrict__ w_conv,
             float* __restrict__ att_out,
             float* __restrict__ att_sc) {
    extern __shared__ char smraw[];
    ulonglong2* w2      = (ulonglong2*)(smraw + OFF_W);
    float*      cc_s    = (float*)(smraw + OFF_CC);
    float*      red     = (float*)(smraw + OFF_RED);
    float*      spad    = (float*)(smraw + OFF_SPAD);
    float*      score_s = (float*)(smraw + OFF_SC);
    float*      q_s     = (float*)(smraw + OFF_Q);
    float*      wl_s    = (float*)(smraw + OFF_WL);
    float*      wred    = (float*)(smraw + OFF_WRED);

    const int tid  = threadIdx.x;
    const int b    = blockIdx.x >> 4;       // batch
    const int sub  = blockIdx.x & 15;       // 32-d slice
    const int d0   = sub << 5;
    const int warp = tid >> 5, lane = tid & 31;
    const int dg   = warp >> 1;                       // 0..3 : 8-d group
    const int tslot = ((warp & 1) << 5) | lane;       // 0..63
    const int t0   = tslot << 3;                      // 8 t per thread
    const int ol   = out_len[b];

    // weights: per local d (32), 16 pairs for w0 then 16 for w1
    for (int e = tid; e < 32 * 32; e += NTHR) {
        int d = e >> 5, j = e & 31, i = j & 15;
        const float* wb = w_conv + (size_t)(d0 + d) * 62 + ((j < 16) ? 0 : 31);
        float wm1 = (i > 0)  ? wb[2*i - 1] : 0.0f;
        float w0v = wb[2*i];
        float wp1 = (i < 15) ? wb[2*i + 1] : 0.0f;
        ulonglong2 v;
        v.x = pack2(wm1, w0v);
        v.y = pack2(w0v, wp1);
        w2[(d << 5) + j] = v;
    }
    if (tid < 32) {
        wl_s[tid] = w_lin[d0 + tid];
        q_s[tid]  = (0 < ol) ? mel[(size_t)(b * DEC_T) * NDIM + d0 + tid] : 0.0f;
    }
    for (int i = tid; i < PADTOT; i += NTHR) spad[i] = 0.0f;
    for (int i = tid; i < 32 * 512; i += NTHR) cc_s[i] = 0.0f;
    __syncthreads();

    unsigned bar_target = 0;

    for (int s = 0; s < DEC_T; ++s) {
        const int par = s & 1;

        // ===== phase A: conv0(score) + incremental conv1(cum) over 32 d =====
        u64 Ws[20];
        {
            const float4* sp4 = reinterpret_cast<const float4*>(spad + t0);
#pragma unroll
            for (int j = 0; j < 10; ++j) {
                float4 f = sp4[j];
                Ws[2*j]   = pack2(f.x, f.y);
                Ws[2*j+1] = pack2(f.z, f.w);
            }
        }

        float lacc0=0.f,lacc1=0.f,lacc2=0.f,lacc3=0.f;
        float lacc4=0.f,lacc5=0.f,lacc6=0.f,lacc7=0.f;

#pragma unroll 1
        for (int dd = 0; dd < 8; ++dd) {
            const int d = (dg << 3) + dd;
            float* ccp = cc_s + (d << 9) + t0;
            float4 cc0 = reinterpret_cast<float4*>(ccp)[0];
            float4 cc1 = reinterpret_cast<float4*>(ccp)[1];
            const ulonglong2* wr = w2 + (d << 5);

            u64 as0=0,as1=0,as2=0,as3=0,as4=0,as5=0,as6=0,as7=0;
            u64 av0=0,av1=0,av2=0,av3=0,av4=0,av5=0,av6=0,av7=0;
#pragma unroll
            for (int i = 0; i < 16; ++i) {
                ulonglong2 A  = wr[i];
                ulonglong2 Bv = wr[16 + i];
                as0 = ffma2(A.x,  Ws[i],     as0);
                as1 = ffma2(A.y,  Ws[i + 1], as1);
                as2 = ffma2(A.x,  Ws[i + 1], as2);
                as3 = ffma2(A.y,  Ws[i + 2], as3);
                as4 = ffma2(A.x,  Ws[i + 2], as4);
                as5 = ffma2(A.y,  Ws[i + 3], as5);
                as6 = ffma2(A.x,  Ws[i + 3], as6);
                as7 = ffma2(A.y,  Ws[i + 4], as7);
                av0 = ffma2(Bv.x, Ws[i],     av0);
                av1 = ffma2(Bv.y, Ws[i + 1], av1);
                av2 = ffma2(Bv.x, Ws[i + 1], av2);
                av3 = ffma2(Bv.y, Ws[i + 2], av3);
                av4 = ffma2(Bv.x, Ws[i + 2], av4);
                av5 = ffma2(Bv.y, Ws[i + 3], av5);
                av6 = ffma2(Bv.x, Ws[i + 3], av6);
                av7 = ffma2(Bv.y, Ws[i + 4], av7);
            }
            const float qd = q_s[d], wld = wl_s[d];

            float c0 = cc0.x + hsum2(av0);
            float c1 = cc0.y + hsum2(av1);
            float c2 = cc0.z + hsum2(av2);
            float c3 = cc0.w + hsum2(av3);
            float c4 = cc1.x + hsum2(av4);
            float c5 = cc1.y + hsum2(av5);
            float c6 = cc1.z + hsum2(av6);
            float c7 = cc1.w + hsum2(av7);
            reinterpret_cast<float4*>(ccp)[0] = make_float4(c0, c1, c2, c3);
            reinterpret_cast<float4*>(ccp)[1] = make_float4(c4, c5, c6, c7);

            lacc0 = fmaf(wld, fast_tanh(qd + hsum2(as0) + c0), lacc0);
            lacc1 = fmaf(wld, fast_tanh(qd + hsum2(as1) + c1), lacc1);
            lacc2 = fmaf(wld, fast_tanh(qd + hsum2(as2) + c2), lacc2);
            lacc3 = fmaf(wld, fast_tanh(qd + hsum2(as3) + c3), lacc3);
            lacc4 = fmaf(wld, fast_tanh(qd + hsum2(as4) + c4), lacc4);
            lacc5 = fmaf(wld, fast_tanh(qd + hsum2(as5) + c5), lacc5);
            lacc6 = fmaf(wld, fast_tanh(qd + hsum2(as6) + c6), lacc6);
            lacc7 = fmaf(wld, fast_tanh(qd + hsum2(as7) + c7), lacc7);
        }
        {
            float* rp = red + (dg << 9) + t0;
            reinterpret_cast<float4*>(rp)[0] = make_float4(lacc0, lacc1, lacc2, lacc3);
            reinterpret_cast<float4*>(rp)[1] = make_float4(lacc4, lacc5, lacc6, lacc7);
        }
        __syncthreads();
#pragma unroll
        for (int k = 0; k < 2; ++k) {
            const int t = tid + (k << 8);
            float lp = red[t] + red[512 + t] + red[1024 + t] + red[1536 + t];
            __stcg(&g_lpart[par][b][sub][t], lp);
        }

        // ===== per-batch barrier (release arrive, acquire poll) =====
        __syncthreads();
        if (tid == 0) {
            bar_target += (unsigned)NSUB;
            asm volatile("red.release.gpu.global.add.u32 [%0], %1;"
                         :: "l"(&g_bar[b]), "r"(1u) : "memory");
            unsigned cur;
            for (;;) {
                asm volatile("ld.acquire.gpu.u32 %0, [%1];"
                             : "=r"(cur) : "l"(&g_bar[b]));
                if ((int)(cur - bar_target) >= 0) break;
                __nanosleep(32);
            }
        }
        __syncthreads();

        // ===== phase B: softmax (no max pass; |logit| <= ~18), ctx, q =====
        float lv0 = 0.0f, lv1 = 0.0f;
#pragma unroll
        for (int j = 0; j < NSUB; ++j) {
            lv0 += __ldcg(&g_lpart[par][b][j][tid]);
            lv1 += __ldcg(&g_lpart[par][b][j][tid + 256]);
        }
        const float e0 = __expf(lv0);
        const float e1 = __expf(lv1);
        float ssum = e0 + e1;
#pragma unroll
        for (int o = 16; o; o >>= 1) ssum += __shfl_xor_sync(0xffffffffu, ssum, o);
        if (lane == 0) wred[warp] = ssum;
        __syncthreads();
        if (warp == 0) {
            float v = (lane < 8) ? wred[lane] : 0.0f;
#pragma unroll
            for (int o = 4; o; o >>= 1) v += __shfl_xor_sync(0xffffffffu, v, o);
            if (lane == 0) wred[8] = __fdividef(1.0f, v);
        }
        __syncthreads();
        const float inv = wred[8];
        const float sc0 = e0 * inv, sc1 = e1 * inv;
        score_s[tid]           = sc0;
        score_s[tid + 256]     = sc1;
        spad[PADZ + tid]       = sc0;
        spad[PADZ + tid + 256] = sc1;
        __syncthreads();

        // ctx[b, 32-d slice] = sum_t score[t] * enc[b,t,d0+dl]
        {
            const int dl = tid & 31, tc = tid >> 5;   // 8 chunks of 64 t
            const float* ep = enc + ((size_t)(b * ENC_T + (tc << 6)) * NDIM) + d0 + dl;
            const float* sp = score_s + (tc << 6);
            float a0 = 0.f, a1 = 0.f, a2 = 0.f, a3 = 0.f;
#pragma unroll 4
            for (int j = 0; j < 64; j += 4) {
                a0 = fmaf(sp[j],     ep[(size_t)(j)     * NDIM], a0);
                a1 = fmaf(sp[j + 1], ep[(size_t)(j + 1) * NDIM], a1);
                a2 = fmaf(sp[j + 2], ep[(size_t)(j + 2) * NDIM], a2);
                a3 = fmaf(sp[j + 3], ep[(size_t)(j + 3) * NDIM], a3);
            }
            red[tid] = (a0 + a1) + (a2 + a3);
        }
        __syncthreads();
        const int rowo = (b << 10) + s;
        if (tid < 32) {
            float c = red[tid];
#pragma unroll
            for (int g = 1; g < 8; ++g) c += red[(g << 5) + tid];
            const int d = d0 + tid;
            att_out[(size_t)rowo * NDIM + d] = (s < ol) ? c : 0.0f;
            float mm2 = 0.0f;
            if (s + 1 < ol)
                mm2 = (s + 1 < DEC_T) ? mel[(size_t)(rowo + 1) * NDIM + d] : 0.0f;
            q_s[tid] = c + mm2;
        }
        if (sub == 0) {
            att_sc[(size_t)rowo * ENC_T + tid]       = sc0;
            att_sc[(size_t)rowo * ENC_T + tid + 256] = sc1;
        }
        __syncthreads();
    }
}

extern "C" void kernel_launch(void* const* d_in, const int* in_sizes, int n_in,
                              void* d_out, int out_size) {
    const float* enc     = (const float*)d_in[0];
    const float* mel     = (const float*)d_in[1];
    const int*   out_len = (const int*)  d_in[3];
    const float* wlin    = (const float*)d_in[4];
    const float* wconv   = (const float*)d_in[5];
    float* att_out = (float*)d_out;
    float* att_sc  = att_out + (size_t)NB * DEC_T * NDIM;

    cudaFuncSetAttribute(attn_persist,
                         cudaFuncAttributeMaxDynamicSharedMemorySize, SM_BYTES);

    attn_init<<<1, 32>>>();
    attn_persist<<<NCTAS, NTHR, SM_BYTES>>>(enc, mel, out_len, wlin, wconv,
                                            att_out, att_sc);
}

// round 8
// speedup vs baseline: 1.5885x; 1.0185x over previous
#include <cuda_runtime.h>
#include <cuda_bf16.h>

#define NB     16
#define ENC_T  512
#define DEC_T  1024
#define NDIM   512
#define NSUB   18
#define NCTAS  (NB * NSUB)   // 288
#define NTHR   256
#define PADZ   16
#define PADTOT 544
#define DMAX   29

typedef unsigned long long u64;

// smem layout (bytes per CTA), 16B-aligned
#define OFF_W    0            // 29*32*16 = 14848
#define OFF_CC   14848        // 29*512*4 = 59392
#define OFF_RED  74240        // 4*512*4  = 8192
#define OFF_SPAD 82432        // 544*4    = 2176
#define OFF_SC   84608        // 512*4    = 2048
#define OFF_Q    86656        // 128
#define OFF_WL   86784        // 128
#define OFF_WRED 86912        // 64
#define SM_BYTES 86976

__device__ __forceinline__ u64 pack2(float x, float y) {
    u64 r;
    asm("mov.b64 %0, {%1, %2};" : "=l"(r)
        : "r"(__float_as_uint(x)), "r"(__float_as_uint(y)));
    return r;
}
__device__ __forceinline__ void unpack2(u64 v, float& x, float& y) {
    unsigned a, b;
    asm("mov.b64 {%0, %1}, %2;" : "=r"(a), "=r"(b) : "l"(v));
    x = __uint_as_float(a); y = __uint_as_float(b);
}
__device__ __forceinline__ u64 ffma2(u64 a, u64 b, u64 c) {
    u64 d;
    asm("fma.rn.f32x2 %0, %1, %2, %3;" : "=l"(d) : "l"(a), "l"(b), "l"(c));
    return d;
}
__device__ __forceinline__ float hsum2(u64 v) {
    float x, y; unpack2(v, x, y); return x + y;
}
__device__ __forceinline__ float fast_tanh(float x) {
    float e = __expf(x + x);
    return 1.0f - __fdividef(2.0f, e + 1.0f);
}

// ---------- persistent globals ----------
__device__ float    g_lpart[2][NB][NSUB][ENC_T];
__device__ unsigned g_bar[NB];

__global__ void attn_init() {
    if (threadIdx.x < NB) g_bar[threadIdx.x] = 0;
}

__global__ void __launch_bounds__(NTHR, 2)
attn_persist(const float* __restrict__ enc,
             const float* __restrict__ mel,
             const int*   __restrict__ out_len,
             const float* __restrict__ w_lin,
             const float* __restrict__ w_conv,
             float* __restrict__ att_out,
             float* __restrict__ att_sc) {
    extern __shared__ char smraw[];
    ulonglong2* w2      = (ulonglong2*)(smraw + OFF_W);
    float*      cc_s    = (float*)(smraw + OFF_CC);
    float*      red     = (float*)(smraw + OFF_RED);
    float*      spad    = (float*)(smraw + OFF_SPAD);
    float*      score_s = (float*)(smraw + OFF_SC);
    float*      q_s     = (float*)(smraw + OFF_Q);
    float*      wl_s    = (float*)(smraw + OFF_WL);
    float*      wred    = (float*)(smraw + OFF_WRED);

    const int tid  = threadIdx.x;
    const int b    = blockIdx.x & 15;       // batch  (adjacent bids -> different batches)
    const int sub  = blockIdx.x >> 4;       // 0..17 d-slice
    const int nd   = (sub < 8) ? 29 : 28;
    const int d0   = (sub < 8) ? 29 * sub : 232 + 28 * (sub - 8);
    const int warp = tid >> 5, lane = tid & 31;
    const int dg   = warp >> 1;                       // 0..3 d-group
    const int tslot = ((warp & 1) << 5) | lane;       // 0..63
    const int t0   = tslot << 3;                      // 8 t per thread
    const int ol   = out_len[b];

    // weights: per local d, 16 pairs for w0 then 16 for w1 (zero-padded edges)
    for (int e = tid; e < nd * 32; e += NTHR) {
        int d = e >> 5, j = e & 31, i = j & 15;
        const float* wb = w_conv + (size_t)(d0 + d) * 62 + ((j < 16) ? 0 : 31);
        float wm1 = (i > 0)  ? wb[2*i - 1] : 0.0f;
        float w0v = wb[2*i];
        float wp1 = (i < 15) ? wb[2*i + 1] : 0.0f;
        ulonglong2 v;
        v.x = pack2(wm1, w0v);
        v.y = pack2(w0v, wp1);
        w2[(d << 5) + j] = v;
    }
    if (tid < nd) {
        wl_s[tid] = w_lin[d0 + tid];
        q_s[tid]  = (0 < ol) ? mel[(size_t)(b * DEC_T) * NDIM + d0 + tid] : 0.0f;
    }
    for (int i = tid; i < PADTOT; i += NTHR) spad[i] = 0.0f;
    for (int i = tid; i < nd * 512; i += NTHR) cc_s[i] = 0.0f;
    __syncthreads();

    unsigned bar_target = 0;

    for (int s = 0; s < DEC_T; ++s) {
        const int par = s & 1;

        // ===== phase A: conv0(score) + incremental conv1(cum) =====
        u64 Ws[20];
        {
            const float4* sp4 = reinterpret_cast<const float4*>(spad + t0);
#pragma unroll
            for (int j = 0; j < 10; ++j) {
                float4 f = sp4[j];
                Ws[2*j]   = pack2(f.x, f.y);
                Ws[2*j+1] = pack2(f.z, f.w);
            }
        }

        float lacc0=0.f,lacc1=0.f,lacc2=0.f,lacc3=0.f;
        float lacc4=0.f,lacc5=0.f,lacc6=0.f,lacc7=0.f;

#pragma unroll 1
        for (int d = dg; d < nd; d += 4) {
            float* ccp = cc_s + (d << 9) + t0;
            float4 cc0 = reinterpret_cast<float4*>(ccp)[0];
            float4 cc1 = reinterpret_cast<float4*>(ccp)[1];
            const ulonglong2* wr = w2 + (d << 5);

            u64 as0=0,as1=0,as2=0,as3=0,as4=0,as5=0,as6=0,as7=0;
            u64 av0=0,av1=0,av2=0,av3=0,av4=0,av5=0,av6=0,av7=0;
#pragma unroll
            for (int i = 0; i < 16; ++i) {
                ulonglong2 A  = wr[i];
                ulonglong2 Bv = wr[16 + i];
                as0 = ffma2(A.x,  Ws[i],     as0);
                as1 = ffma2(A.y,  Ws[i + 1], as1);
                as2 = ffma2(A.x,  Ws[i + 1], as2);
                as3 = ffma2(A.y,  Ws[i + 2], as3);
                as4 = ffma2(A.x,  Ws[i + 2], as4);
                as5 = ffma2(A.y,  Ws[i + 3], as5);
                as6 = ffma2(A.x,  Ws[i + 3], as6);
                as7 = ffma2(A.y,  Ws[i + 4], as7);
                av0 = ffma2(Bv.x, Ws[i],     av0);
                av1 = ffma2(Bv.y, Ws[i + 1], av1);
                av2 = ffma2(Bv.x, Ws[i + 1], av2);
                av3 = ffma2(Bv.y, Ws[i + 2], av3);
                av4 = ffma2(Bv.x, Ws[i + 2], av4);
                av5 = ffma2(Bv.y, Ws[i + 3], av5);
                av6 = ffma2(Bv.x, Ws[i + 3], av6);
                av7 = ffma2(Bv.y, Ws[i + 4], av7);
            }
            const float qd = q_s[d], wld = wl_s[d];

            float c0 = cc0.x + hsum2(av0);
            float c1 = cc0.y + hsum2(av1);
            float c2 = cc0.z + hsum2(av2);
            float c3 = cc0.w + hsum2(av3);
            float c4 = cc1.x + hsum2(av4);
            float c5 = cc1.y + hsum2(av5);
            float c6 = cc1.z + hsum2(av6);
            float c7 = cc1.w + hsum2(av7);
            reinterpret_cast<float4*>(ccp)[0] = make_float4(c0, c1, c2, c3);
            reinterpret_cast<float4*>(ccp)[1] = make_float4(c4, c5, c6, c7);

            lacc0 = fmaf(wld, fast_tanh(qd + hsum2(as0) + c0), lacc0);
            lacc1 = fmaf(wld, fast_tanh(qd + hsum2(as1) + c1), lacc1);
            lacc2 = fmaf(wld, fast_tanh(qd + hsum2(as2) + c2), lacc2);
            lacc3 = fmaf(wld, fast_tanh(qd + hsum2(as3) + c3), lacc3);
            lacc4 = fmaf(wld, fast_tanh(qd + hsum2(as4) + c4), lacc4);
            lacc5 = fmaf(wld, fast_tanh(qd + hsum2(as5) + c5), lacc5);
            lacc6 = fmaf(wld, fast_tanh(qd + hsum2(as6) + c6), lacc6);
            lacc7 = fmaf(wld, fast_tanh(qd + hsum2(as7) + c7), lacc7);
        }
        {
            float* rp = red + (dg << 9) + t0;
            reinterpret_cast<float4*>(rp)[0] = make_float4(lacc0, lacc1, lacc2, lacc3);
            reinterpret_cast<float4*>(rp)[1] = make_float4(lacc4, lacc5, lacc6, lacc7);
        }
        __syncthreads();
#pragma unroll
        for (int k = 0; k < 2; ++k) {
            const int t = tid + (k << 8);
            float lp = red[t] + red[512 + t] + red[1024 + t] + red[1536 + t];
            __stcg(&g_lpart[par][b][sub][t], lp);
        }

        // ===== per-batch barrier (release arrive, acquire poll) =====
        __syncthreads();
        if (tid == 0) {
            bar_target += (unsigned)NSUB;
            asm volatile("red.release.gpu.global.add.u32 [%0], %1;"
                         :: "l"(&g_bar[b]), "r"(1u) : "memory");
            unsigned cur;
            for (;;) {
                asm volatile("ld.acquire.gpu.u32 %0, [%1];"
                             : "=r"(cur) : "l"(&g_bar[b]));
                if ((int)(cur - bar_target) >= 0) break;
                __nanosleep(32);
            }
        }
        __syncthreads();

        // ===== phase B: softmax (no max pass; |logit| <= ~18), ctx, q =====
        float lv0 = 0.0f, lv1 = 0.0f;
#pragma unroll
        for (int j = 0; j < NSUB; ++j) {
            lv0 += __ldcg(&g_lpart[par][b][j][tid]);
            lv1 += __ldcg(&g_lpart[par][b][j][tid + 256]);
        }
        const float e0 = __expf(lv0);
        const float e1 = __expf(lv1);
        float ssum = e0 + e1;
#pragma unroll
        for (int o = 16; o; o >>= 1) ssum += __shfl_xor_sync(0xffffffffu, ssum, o);
        if (lane == 0) wred[warp] = ssum;
        __syncthreads();
        if (warp == 0) {
            float v = (lane < 8) ? wred[lane] : 0.0f;
#pragma unroll
            for (int o = 4; o; o >>= 1) v += __shfl_xor_sync(0xffffffffu, v, o);
            if (lane == 0) wred[8] = __fdividef(1.0f, v);
        }
        __syncthreads();
        const float inv = wred[8];
        const float sc0 = e0 * inv, sc1 = e1 * inv;
        score_s[tid]           = sc0;
        score_s[tid + 256]     = sc1;
        spad[PADZ + tid]       = sc0;
        spad[PADZ + tid + 256] = sc1;
        __syncthreads();

        // ctx[b, d-slice] = sum_t score[t] * enc[b,t,d0+dl]
        {
            const int dl = tid & 31, tc = tid >> 5;   // 8 chunks of 64 t
            if (dl < nd) {
                const float* ep = enc + ((size_t)(b * ENC_T + (tc << 6)) * NDIM) + d0 + dl;
                const float* sp = score_s + (tc << 6);
                float a0 = 0.f, a1 = 0.f, a2 = 0.f, a3 = 0.f;
#pragma unroll 4
                for (int j = 0; j < 64; j += 4) {
                    a0 = fmaf(sp[j],     ep[(size_t)(j)     * NDIM], a0);
                    a1 = fmaf(sp[j + 1], ep[(size_t)(j + 1) * NDIM], a1);
                    a2 = fmaf(sp[j + 2], ep[(size_t)(j + 2) * NDIM], a2);
                    a3 = fmaf(sp[j + 3], ep[(size_t)(j + 3) * NDIM], a3);
                }
                red[tid] = (a0 + a1) + (a2 + a3);
            }
        }
        __syncthreads();
        const int rowo = (b << 10) + s;
        if (tid < nd) {
            float c = red[tid];
#pragma unroll
            for (int g = 1; g < 8; ++g) c += red[(g << 5) + tid];
            const int d = d0 + tid;
            att_out[(size_t)rowo * NDIM + d] = (s < ol) ? c : 0.0f;
            float mm2 = 0.0f;
            if (s + 1 < ol)
                mm2 = (s + 1 < DEC_T) ? mel[(size_t)(rowo + 1) * NDIM + d] : 0.0f;
            q_s[tid] = c + mm2;
        }
        if (sub == 0) {
            att_sc[(size_t)rowo * ENC_T + tid]       = sc0;
            att_sc[(size_t)rowo * ENC_T + tid + 256] = sc1;
        }
        __syncthreads();
    }
}

extern "C" void kernel_launch(void* const* d_in, const int* in_sizes, int n_in,
                              void* d_out, int out_size) {
    const float* enc     = (const float*)d_in[0];
    const float* mel     = (const float*)d_in[1];
    const int*   out_len = (const int*)  d_in[3];
    const float* wlin    = (const float*)d_in[4];
    const float* wconv   = (const float*)d_in[5];
    float* att_out = (float*)d_out;
    float* att_sc  = att_out + (size_t)NB * DEC_T * NDIM;

    cudaFuncSetAttribute(attn_persist,
                         cudaFuncAttributeMaxDynamicSharedMemorySize, SM_BYTES);

    attn_init<<<1, 32>>>();
    attn_persist<<<NCTAS, NTHR, SM_BYTES>>>(enc, mel, out_len, wlin, wconv,
                                            att_out, att_sc);
}